// round 14
// baseline (speedup 1.0000x reference)
#include <cuda_runtime.h>
#include <cuda_bf16.h>
#include <cuda_fp16.h>
#include <math.h>
#include <stdint.h>

#define NN 65536
#define EE 1048576
#define GG 32
#define SS 2048
#define HH 128
#define CC 40

// ---------------- scratch (device globals; no runtime allocation) ----------
__device__ __align__(16) __nv_bfloat16 g_xhi[(size_t)NN * HH];
__device__ __align__(16) __nv_bfloat16 g_xlo[(size_t)NN * HH];
__device__ __align__(16) __nv_bfloat16 g_pAhi[(size_t)NN * HH];
__device__ __align__(16) __nv_bfloat16 g_pAlo[(size_t)NN * HH];
__device__ __align__(16) __nv_bfloat16 g_pBhi[(size_t)NN * HH];
__device__ __align__(16) __nv_bfloat16 g_pBlo[(size_t)NN * HH];
__device__ __align__(16) __nv_bfloat16 g_wdynhi[GG * HH * HH];
__device__ __align__(16) __nv_bfloat16 g_wdynlo[GG * HH * HH];
__device__ __align__(16) __nv_bfloat16 g_cwhi[3 * HH * HH];
__device__ __align__(16) __nv_bfloat16 g_cwlo[3 * HH * HH];
__device__ __align__(16) __half g_hw[(size_t)NN * HH];   // 16 MB, pre-scaled by dis
__device__ float  g_dis[NN];
__device__ int    g_counts[NN];
__device__ int    g_off[NN + 1];
__device__ int    g_cursor[NN];
__device__ int    g_col[EE];               // 4 MB
__device__ int    g_blocksum[256];
__device__ int    g_is64;

// ---------------- helpers ----------------------------------------------------
__device__ __forceinline__ uint32_t smem_to_u32(const void* p) {
    uint32_t a;
    asm("{ .reg .u64 t; cvta.to.shared.u64 t, %1; cvt.u32.u64 %0, t; }"
        : "=r"(a) : "l"(p));
    return a;
}
__device__ __forceinline__ uint64_t gptr(const void* p) {
    uint64_t r;
    asm("cvta.to.global.u64 %0, %1;" : "=l"(r) : "l"(p));
    return r;
}
#define CP_ASYNC16(dst, src) \
    asm volatile("cp.async.cg.shared.global [%0], [%1], 16;" \
        :: "r"(dst), "l"(src))
#define CP_COMMIT()  asm volatile("cp.async.commit_group;")
#define CP_WAIT0()   asm volatile("cp.async.wait_group 0;" ::: "memory")

#define LDSM_X4(r0, r1, r2, r3, addr) \
    asm volatile("ldmatrix.sync.aligned.m8n8.x4.shared.b16 {%0,%1,%2,%3}, [%4];" \
        : "=r"(r0), "=r"(r1), "=r"(r2), "=r"(r3) : "r"(addr))
#define LDSM_X4_T(r0, r1, r2, r3, addr) \
    asm volatile("ldmatrix.sync.aligned.m8n8.x4.trans.shared.b16 {%0,%1,%2,%3}, [%4];" \
        : "=r"(r0), "=r"(r1), "=r"(r2), "=r"(r3) : "r"(addr))
#define MMA_BF16(d, a, b0v, b1v) \
    asm volatile("mma.sync.aligned.m16n8k16.row.col.f32.bf16.bf16.f32 " \
        "{%0,%1,%2,%3}, {%4,%5,%6,%7}, {%8,%9}, {%0,%1,%2,%3};" \
        : "+f"((d)[0]), "+f"((d)[1]), "+f"((d)[2]), "+f"((d)[3]) \
        : "r"((a)[0]), "r"((a)[1]), "r"((a)[2]), "r"((a)[3]), \
          "r"(b0v), "r"(b1v))

__device__ __forceinline__ uint32_t pack_bf16x2(float e0, float e1) {
    uint32_t r;
    asm("cvt.rn.bf16x2.f32 %0, %1, %2;" : "=r"(r) : "f"(e1), "f"(e0));
    return r;
}
__device__ __forceinline__ void split2(float e0, float e1,
                                       uint32_t& hi, uint32_t& lo) {
    float h0 = __bfloat162float(__float2bfloat16_rn(e0));
    float h1 = __bfloat162float(__float2bfloat16_rn(e1));
    hi = pack_bf16x2(h0, h1);
    lo = pack_bf16x2(e0 - h0, e1 - h1);
}

// ---------------- preprocessing kernels -------------------------------------
__global__ void wdyn_kernel(const float* __restrict__ w0,
                            const float* __restrict__ b0,
                            const float* __restrict__ emeta,
                            const int* __restrict__ ei) {
    int idx = blockIdx.x * blockDim.x + threadIdx.x;
    if (idx < NN) g_counts[idx] = 0;
    if (blockIdx.x == 0 && threadIdx.x < 32) {
        int nz = 0;
#pragma unroll
        for (int q = 0; q < 4; q++) nz |= ei[1 + 2 * (threadIdx.x + q * 32)];
        unsigned any = __ballot_sync(0xFFFFFFFFu, nz != 0);
        if (threadIdx.x == 0) g_is64 = (any == 0);
    }
    if (idx >= GG * HH * HH / 2) return;
    int base = idx * 2;
    int g   = base >> 14;
    int rem = base & 16383;
    int f   = rem >> 7;
    int h   = rem & 127;
    float ga = emeta[g * HH + h];
    float gb = emeta[g * HH + h + 1];
    float v0 = fmaxf(fmaf(w0[f], ga, b0[rem]), 0.0f);
    float v1 = fmaxf(fmaf(w0[f], gb, b0[rem + 1]), 0.0f);
    uint32_t hi, lo;
    split2(v0, v1, hi, lo);
    ((uint32_t*)g_wdynhi)[idx] = hi;
    ((uint32_t*)g_wdynlo)[idx] = lo;
}

#define XQ (NN * HH / 4)
#define WQ (3 * HH * HH / 4)
__global__ void split_xw_kernel(const float* __restrict__ x,
                                const float* __restrict__ cw) {
    int i = blockIdx.x * blockDim.x + threadIdx.x;
    if (i < XQ) {
        float4 v = ((const float4*)x)[i];
        uint32_t h01, l01, h23, l23;
        split2(v.x, v.y, h01, l01);
        split2(v.z, v.w, h23, l23);
        ((uint2*)g_xhi)[i] = make_uint2(h01, h23);
        ((uint2*)g_xlo)[i] = make_uint2(l01, l23);
    } else if (i < XQ + WQ) {
        int j = i - XQ;
        float4 v = ((const float4*)cw)[j];
        uint32_t h01, l01, h23, l23;
        split2(v.x, v.y, h01, l01);
        split2(v.z, v.w, h23, l23);
        ((uint2*)g_cwhi)[j] = make_uint2(h01, h23);
        ((uint2*)g_cwlo)[j] = make_uint2(l01, l23);
    }
}

__device__ __forceinline__ int load_idx(const void* ei, long long pos) {
    if (g_is64) return (int)((const long long*)ei)[pos];
    return ((const int*)ei)[pos];
}

__global__ void count_kernel(const void* __restrict__ ei) {
    int e = blockIdx.x * blockDim.x + threadIdx.x;
    if (e >= EE) return;
    int d = load_idx(ei, (long long)EE + e);
    atomicAdd(&g_counts[d], 1);
}

// ---- hierarchical scan (A: per-block sums, C: merged scan + expand) --------
__global__ void scanA_kernel() {
    __shared__ int sh[256];
    int t = threadIdx.x;
    int v = g_counts[blockIdx.x * 256 + t];
    sh[t] = v;
    __syncthreads();
    for (int d = 128; d > 0; d >>= 1) {
        if (t < d) sh[t] += sh[t + d];
        __syncthreads();
    }
    if (t == 0) g_blocksum[blockIdx.x] = sh[0];
}

__global__ void scanC_kernel() {
    __shared__ int sh[256];
    __shared__ int sPre;
    __shared__ int sTot;
    int t = threadIdx.x;

    // block-level prefix of blocksums (masked reduce) + total
    int bs = g_blocksum[t];
    sh[t] = (t < blockIdx.x) ? bs : 0;
    __syncthreads();
    for (int d = 128; d > 0; d >>= 1) {
        if (t < d) sh[t] += sh[t + d];
        __syncthreads();
    }
    if (t == 0) sPre = sh[0];
    __syncthreads();
    sh[t] = bs;
    __syncthreads();
    for (int d = 128; d > 0; d >>= 1) {
        if (t < d) sh[t] += sh[t + d];
        __syncthreads();
    }
    if (t == 0) sTot = sh[0];
    __syncthreads();

    int i = blockIdx.x * 256 + t;
    int c = g_counts[i];
    sh[t] = c;
    __syncthreads();
    for (int d = 1; d < 256; d <<= 1) {
        int v = 0;
        if (t >= d) v = sh[t - d];
        __syncthreads();
        sh[t] += v;
        __syncthreads();
    }
    int run = sPre + sh[t] - c;
    g_off[i]    = run;
    g_cursor[i] = run;
    g_dis[i]    = rsqrtf((float)(c + 1));
    if (blockIdx.x == 255 && t == 255) g_off[NN] = sTot;
}

__global__ void fill_kernel(const void* __restrict__ ei) {
    int e = blockIdx.x * blockDim.x + threadIdx.x;
    if (e >= EE) return;
    int sidx = load_idx(ei, e);
    int d    = load_idx(ei, (long long)EE + e);
    int p = atomicAdd(&g_cursor[d], 1);
    g_col[p] = sidx;
}

// ---------------- shared GEMM compute (64Mx128N tile, split-bf16) -----------
__device__ __forceinline__ void gemm_tile_compute(
    uint32_t sb, uint32_t aHiOff, uint32_t aLoOff,
    uint32_t bHiOff, uint32_t bLoOff,
    int lane, int m0, int n0, float acc[2][4][4]) {
    int lr = lane & 15;
    int hc = lane >> 4;
    int sx = lane & 7;
#pragma unroll
    for (int ks = 0; ks < 8; ks++) {
        int k0 = ks * 16;
        int chA = ((k0 >> 3) + hc) ^ sx;

        uint32_t aH[2][4], aL[2][4];
#pragma unroll
        for (int mi = 0; mi < 2; mi++) {
            int r = m0 + mi * 16 + lr;
            uint32_t off = (uint32_t)(r * 256 + (chA << 4));
            LDSM_X4(aH[mi][0], aH[mi][1], aH[mi][2], aH[mi][3],
                    sb + aHiOff + off);
            LDSM_X4(aL[mi][0], aL[mi][1], aL[mi][2], aL[mi][3],
                    sb + aLoOff + off);
        }
        uint32_t bH[2][4], bL[2][4];
#pragma unroll
        for (int bi = 0; bi < 2; bi++) {
            int r = k0 + lr;
            int ch = ((n0 >> 3) + bi * 2 + hc) ^ sx;
            uint32_t off = (uint32_t)(r * 256 + (ch << 4));
            LDSM_X4_T(bH[bi][0], bH[bi][1], bH[bi][2], bH[bi][3],
                      sb + bHiOff + off);
            LDSM_X4_T(bL[bi][0], bL[bi][1], bL[bi][2], bL[bi][3],
                      sb + bLoOff + off);
        }
#pragma unroll
        for (int mi = 0; mi < 2; mi++)
#pragma unroll
            for (int ni = 0; ni < 4; ni++) {
                uint32_t bh0 = bH[ni >> 1][(ni & 1) * 2 + 0];
                uint32_t bh1 = bH[ni >> 1][(ni & 1) * 2 + 1];
                uint32_t bl0 = bL[ni >> 1][(ni & 1) * 2 + 0];
                uint32_t bl1 = bL[ni >> 1][(ni & 1) * 2 + 1];
                MMA_BF16(acc[mi][ni], aH[mi], bh0, bh1);
                MMA_BF16(acc[mi][ni], aL[mi], bh0, bh1);
                MMA_BF16(acc[mi][ni], aH[mi], bl0, bl1);
            }
    }
}

// ---------------- common SMEM layout for persistent GEMMs -------------------
#define CB_HI 0
#define CB_LO 32768
#define CA_HI 65536
#define CA_LO 81920
#define GEMM_SMEM 98304

__device__ __forceinline__ void conv_load_A(
    uint32_t sb, const __nv_bfloat16* Ahi, const __nv_bfloat16* Alo,
    int t, size_t row0) {
#pragma unroll
    for (int q = 0; q < 4; q++) {
        int idx = t + q * 256;
        int row = idx >> 4;
        int ch  = idx & 15;
        uint32_t off = (uint32_t)(row * 256 + ((ch ^ (row & 7)) << 4));
        size_t gsrc = (row0 + row) * HH + ch * 8;
        CP_ASYNC16(sb + CA_HI + off, gptr(Ahi + gsrc));
        CP_ASYNC16(sb + CA_LO + off, gptr(Alo + gsrc));
    }
    CP_COMMIT();
}

__device__ __forceinline__ void load_B_resident(
    uint32_t sb, const __nv_bfloat16* Bhi, const __nv_bfloat16* Blo, int t) {
#pragma unroll
    for (int q = 0; q < 8; q++) {
        int idx = t + q * 256;
        int row = idx >> 4;
        int ch  = idx & 15;
        uint32_t off = (uint32_t)(row * 256 + ((ch ^ (row & 7)) << 4));
        size_t gsrc = (size_t)row * HH + ch * 8;
        CP_ASYNC16(sb + CB_HI + off, gptr(Bhi + gsrc));
        CP_ASYNC16(sb + CB_LO + off, gptr(Blo + gsrc));
    }
    CP_COMMIT();
}

// ---------------- gemm0: persistent per-group, pair output ------------------
// grid (8, GG); each CTA holds its group's Wdyn tile and does 4 A-tiles.
__global__ void __launch_bounds__(256, 2)
gemm0_kernel(const __nv_bfloat16* __restrict__ Ahi,
             const __nv_bfloat16* __restrict__ Alo,
             const __nv_bfloat16* __restrict__ Bhi,
             const __nv_bfloat16* __restrict__ Blo,
             __nv_bfloat16* __restrict__ Chi,
             __nv_bfloat16* __restrict__ Clo) {
    extern __shared__ char smchar[];
    uint32_t sb = smem_to_u32(smchar);
    int t = threadIdx.x;
    int wid = t >> 5;
    int lane = t & 31;
    int m0 = (wid >> 2) * 32;
    int n0 = (wid & 3) * 32;
    int erow = lane >> 2;
    int ecol = (lane & 3) * 2;
    int group = blockIdx.y;

    load_B_resident(sb, Bhi + (size_t)group * HH * HH,
                        Blo + (size_t)group * HH * HH, t);

    size_t gbase = (size_t)group * SS;
    conv_load_A(sb, Ahi, Alo, t, gbase + (size_t)blockIdx.x * 64);

#pragma unroll 1
    for (int q = 0; q < 4; q++) {
        size_t row0 = gbase + (size_t)(blockIdx.x + q * 8) * 64;
        CP_WAIT0();
        __syncthreads();

        float acc[2][4][4];
#pragma unroll
        for (int mi = 0; mi < 2; mi++)
#pragma unroll
            for (int ni = 0; ni < 4; ni++)
#pragma unroll
                for (int j = 0; j < 4; j++) acc[mi][ni][j] = 0.0f;

        gemm_tile_compute(sb, CA_HI, CA_LO, CB_HI, CB_LO,
                          lane, m0, n0, acc);
        __syncthreads();

        if (q < 3)
            conv_load_A(sb, Ahi, Alo, t,
                        gbase + (size_t)(blockIdx.x + (q + 1) * 8) * 64);

#pragma unroll
        for (int mi = 0; mi < 2; mi++)
#pragma unroll
            for (int ni = 0; ni < 4; ni++) {
                size_t r = row0 + m0 + mi * 16 + erow;
                int c = n0 + ni * 8 + ecol;
                uint32_t hi, lo;
                split2(acc[mi][ni][0], acc[mi][ni][1], hi, lo);
                *(uint32_t*)(Chi + r * HH + c) = hi;
                *(uint32_t*)(Clo + r * HH + c) = lo;
                split2(acc[mi][ni][2], acc[mi][ni][3], hi, lo);
                *(uint32_t*)(Chi + (r + 8) * HH + c) = hi;
                *(uint32_t*)(Clo + (r + 8) * HH + c) = lo;
            }
    }
}

// ---------------- conv GEMM: persistent, B resident, fp16*dis output --------
#define NTILES (NN / 64)
#define CONV_GRID 296

__global__ void __launch_bounds__(256, 2)
gemm_conv_kernel(const __nv_bfloat16* __restrict__ Ahi,
                 const __nv_bfloat16* __restrict__ Alo,
                 const __nv_bfloat16* __restrict__ Bhi,
                 const __nv_bfloat16* __restrict__ Blo,
                 __half* __restrict__ C) {
    extern __shared__ char smchar[];
    uint32_t sb = smem_to_u32(smchar);
    int t = threadIdx.x;
    int wid = t >> 5;
    int lane = t & 31;
    int m0 = (wid >> 2) * 32;
    int n0 = (wid & 3) * 32;
    int erow = lane >> 2;
    int ecol = (lane & 3) * 2;

    load_B_resident(sb, Bhi, Blo, t);

    int tile = blockIdx.x;
    conv_load_A(sb, Ahi, Alo, t, (size_t)tile * 64);

    for (; tile < NTILES; tile += CONV_GRID) {
        size_t row0 = (size_t)tile * 64;
        CP_WAIT0();
        __syncthreads();

        float acc[2][4][4];
#pragma unroll
        for (int mi = 0; mi < 2; mi++)
#pragma unroll
            for (int ni = 0; ni < 4; ni++)
#pragma unroll
                for (int j = 0; j < 4; j++) acc[mi][ni][j] = 0.0f;

        gemm_tile_compute(sb, CA_HI, CA_LO, CB_HI, CB_LO,
                          lane, m0, n0, acc);
        __syncthreads();

        int next = tile + CONV_GRID;
        if (next < NTILES)
            conv_load_A(sb, Ahi, Alo, t, (size_t)next * 64);

#pragma unroll
        for (int mi = 0; mi < 2; mi++) {
            size_t rb = row0 + m0 + mi * 16 + erow;
            float dr  = g_dis[rb];
            float dr8 = g_dis[rb + 8];
#pragma unroll
            for (int ni = 0; ni < 4; ni++) {
                int c = n0 + ni * 8 + ecol;
                *(__half2*)(C + rb * HH + c) =
                    __floats2half2_rn(acc[mi][ni][0] * dr,
                                      acc[mi][ni][1] * dr);
                *(__half2*)(C + (rb + 8) * HH + c) =
                    __floats2half2_rn(acc[mi][ni][2] * dr8,
                                      acc[mi][ni][3] * dr8);
            }
        }
    }
}

// ---------------- aggregation: pure gather-sum, 8-deep ----------------------
__global__ void agg_kernel(const __half* __restrict__ hw,
                           const float* __restrict__ bias,
                           __nv_bfloat16* __restrict__ outhi,
                           __nv_bfloat16* __restrict__ outlo) {
    int warp = (blockIdx.x * blockDim.x + threadIdx.x) >> 5;
    int lane = threadIdx.x & 31;
    if (warp >= NN) return;
    int i = warp;
    float di = g_dis[i];

    uint2 ua = ((const uint2*)(hw + (size_t)i * HH))[lane];
    float2 a0 = __half22float2(*(__half2*)&ua.x);
    float2 a1 = __half22float2(*(__half2*)&ua.y);
    float4 acc = make_float4(a0.x, a0.y, a1.x, a1.y);

    int e0 = g_off[i], e1 = g_off[i + 1];
    int e = e0;
    for (; e + 8 <= e1; e += 8) {
        int s[8];
#pragma unroll
        for (int q = 0; q < 8; q++) s[q] = g_col[e + q];
        uint2 u[8];
#pragma unroll
        for (int q = 0; q < 8; q++)
            u[q] = ((const uint2*)(hw + (size_t)s[q] * HH))[lane];
#pragma unroll
        for (int q = 0; q < 8; q++) {
            float2 p = __half22float2(*(__half2*)&u[q].x);
            float2 r = __half22float2(*(__half2*)&u[q].y);
            acc.x += p.x; acc.y += p.y; acc.z += r.x; acc.w += r.y;
        }
    }
    if (e + 4 <= e1) {
        int s[4];
#pragma unroll
        for (int q = 0; q < 4; q++) s[q] = g_col[e + q];
        uint2 u[4];
#pragma unroll
        for (int q = 0; q < 4; q++)
            u[q] = ((const uint2*)(hw + (size_t)s[q] * HH))[lane];
#pragma unroll
        for (int q = 0; q < 4; q++) {
            float2 p = __half22float2(*(__half2*)&u[q].x);
            float2 r = __half22float2(*(__half2*)&u[q].y);
            acc.x += p.x; acc.y += p.y; acc.z += r.x; acc.w += r.y;
        }
        e += 4;
    }
    for (; e < e1; e++) {
        uint2 u = ((const uint2*)(hw + (size_t)g_col[e] * HH))[lane];
        float2 p = __half22float2(*(__half2*)&u.x);
        float2 r = __half22float2(*(__half2*)&u.y);
        acc.x += p.x; acc.y += p.y; acc.z += r.x; acc.w += r.y;
    }

    float4 b = ((const float4*)bias)[lane];
    acc.x = fmaxf(fmaf(acc.x, di, b.x), 0.0f);
    acc.y = fmaxf(fmaf(acc.y, di, b.y), 0.0f);
    acc.z = fmaxf(fmaf(acc.z, di, b.z), 0.0f);
    acc.w = fmaxf(fmaf(acc.w, di, b.w), 0.0f);

    uint32_t h01, l01, h23, l23;
    split2(acc.x, acc.y, h01, l01);
    split2(acc.z, acc.w, h23, l23);
    size_t o = (size_t)i * HH + lane * 4;
    *(uint2*)(outhi + o) = make_uint2(h01, h23);
    *(uint2*)(outlo + o) = make_uint2(l01, l23);
}

// ---------------- final: logits + log_softmax (reads hi/lo pair) ------------
__global__ void final_kernel(const __nv_bfloat16* __restrict__ hhi,
                             const __nv_bfloat16* __restrict__ hlo,
                             const float* __restrict__ w,
                             const float* __restrict__ b,
                             float* __restrict__ out) {
    __shared__ float sWt[HH * CC];
    __shared__ float sB[CC];
    __shared__ float sH[16 * HH];
    __shared__ float sL[16 * CC];
    __shared__ float sLse[16];
    int t = threadIdx.x;
    for (int idx = t; idx < CC * HH; idx += 256) {
        int j = idx / HH, k = idx % HH;
        sWt[k * CC + j] = w[idx];
    }
    if (t < CC) sB[t] = b[t];
    size_t node0 = (size_t)blockIdx.x * 16;
    const uint2* hv = (const uint2*)(hhi + node0 * HH);
    const uint2* lv = (const uint2*)(hlo + node0 * HH);
    for (int i = t; i < 16 * HH / 4; i += 256) {
        uint2 hh = hv[i];
        uint2 ll = lv[i];
        __nv_bfloat162 h0 = *(__nv_bfloat162*)&hh.x;
        __nv_bfloat162 h1 = *(__nv_bfloat162*)&hh.y;
        __nv_bfloat162 l0 = *(__nv_bfloat162*)&ll.x;
        __nv_bfloat162 l1 = *(__nv_bfloat162*)&ll.y;
        sH[i * 4 + 0] = __bfloat162float(h0.x) + __bfloat162float(l0.x);
        sH[i * 4 + 1] = __bfloat162float(h0.y) + __bfloat162float(l0.y);
        sH[i * 4 + 2] = __bfloat162float(h1.x) + __bfloat162float(l1.x);
        sH[i * 4 + 3] = __bfloat162float(h1.y) + __bfloat162float(l1.y);
    }
    __syncthreads();

    for (int idx = t; idx < 16 * CC; idx += 256) {
        int n = idx / CC, j = idx % CC;
        float s = sB[j];
        const float* hr = &sH[n * HH];
#pragma unroll 8
        for (int k = 0; k < HH; k++)
            s = fmaf(hr[k], sWt[k * CC + j], s);
        sL[idx] = s;
    }
    __syncthreads();

    int wp = t >> 5, ln = t & 31;
    for (int n = wp; n < 16; n += 8) {
        float m = -INFINITY;
        for (int j = ln; j < CC; j += 32) m = fmaxf(m, sL[n * CC + j]);
        for (int o = 16; o > 0; o >>= 1) m = fmaxf(m, __shfl_xor_sync(~0u, m, o));
        float s = 0.0f;
        for (int j = ln; j < CC; j += 32) s += expf(sL[n * CC + j] - m);
        for (int o = 16; o > 0; o >>= 1) s += __shfl_xor_sync(~0u, s, o);
        if (ln == 0) sLse[n] = m + logf(s);
    }
    __syncthreads();

    for (int idx = t; idx < 16 * CC; idx += 256) {
        int n = idx / CC;
        out[node0 * CC + idx] = sL[idx] - sLse[n];
    }
}

// ---------------- launch ----------------------------------------------------
extern "C" void kernel_launch(void* const* d_in, const int* in_sizes, int n_in,
                              void* d_out, int out_size) {
    const float* x     = (const float*)d_in[0];
    const void*  ei    = d_in[1];
    const float* emeta = (const float*)d_in[2];
    const float* w0    = (const float*)d_in[4];
    const float* b0    = (const float*)d_in[5];
    const float* convw = (const float*)d_in[6];
    const float* convb = (const float*)d_in[7];
    const float* ltw   = (const float*)d_in[8];
    const float* ltb   = (const float*)d_in[9];
    float* out = (float*)d_out;

    __nv_bfloat16 *xhi, *xlo, *pAhi, *pAlo, *pBhi, *pBlo;
    __nv_bfloat16 *wdhi, *wdlo, *cwhi, *cwlo;
    __half *hw;
    cudaGetSymbolAddress((void**)&xhi,  g_xhi);
    cudaGetSymbolAddress((void**)&xlo,  g_xlo);
    cudaGetSymbolAddress((void**)&pAhi, g_pAhi);
    cudaGetSymbolAddress((void**)&pAlo, g_pAlo);
    cudaGetSymbolAddress((void**)&pBhi, g_pBhi);
    cudaGetSymbolAddress((void**)&pBlo, g_pBlo);
    cudaGetSymbolAddress((void**)&wdhi, g_wdynhi);
    cudaGetSymbolAddress((void**)&wdlo, g_wdynlo);
    cudaGetSymbolAddress((void**)&cwhi, g_cwhi);
    cudaGetSymbolAddress((void**)&cwlo, g_cwlo);
    cudaGetSymbolAddress((void**)&hw,   g_hw);

    cudaFuncSetAttribute(gemm0_kernel,
                         cudaFuncAttributeMaxDynamicSharedMemorySize, GEMM_SMEM);
    cudaFuncSetAttribute(gemm_conv_kernel,
                         cudaFuncAttributeMaxDynamicSharedMemorySize, GEMM_SMEM);

    // slot 3 = gemm0 for ncu (verifies the persistence prediction)
    wdyn_kernel<<<(GG * HH * HH / 2 + 255) / 256, 256>>>(w0, b0, emeta,
                                                         (const int*)ei);  // 0
    split_xw_kernel<<<(XQ + WQ + 255) / 256, 256>>>(x, convw);             // 1
    count_kernel<<<EE / 256, 256>>>(ei);                                   // 2
    gemm0_kernel<<<dim3(8, GG), 256, GEMM_SMEM>>>(                         // 3
        xhi, xlo, wdhi, wdlo, pAhi, pAlo);
    scanA_kernel<<<256, 256>>>();                                          // 4
    scanC_kernel<<<256, 256>>>();                                          // 5
    fill_kernel<<<EE / 256, 256>>>(ei);                                    // 6

    // 3 GCN layers (persistent conv GEMM, B resident)
    __nv_bfloat16* curhi = pAhi; __nv_bfloat16* curlo = pAlo;
    __nv_bfloat16* nxthi = pBhi; __nv_bfloat16* nxtlo = pBlo;
    for (int l = 0; l < 3; l++) {
        gemm_conv_kernel<<<CONV_GRID, 256, GEMM_SMEM>>>(
            curhi, curlo, cwhi + (size_t)l * HH * HH, cwlo + (size_t)l * HH * HH,
            hw);
        agg_kernel<<<NN / 8, 256>>>(hw, convb + (size_t)l * HH, nxthi, nxtlo);
        __nv_bfloat16* th = curhi; curhi = nxthi; nxthi = th;
        __nv_bfloat16* tl = curlo; curlo = nxtlo; nxtlo = tl;
    }

    // logits + log_softmax
    final_kernel<<<NN / 16, 256>>>(curhi, curlo, ltw, ltb, out);
}

// round 16
// speedup vs baseline: 1.0263x; 1.0263x over previous
#include <cuda_runtime.h>
#include <cuda_bf16.h>
#include <cuda_fp16.h>
#include <math.h>
#include <stdint.h>

#define NN 65536
#define EE 1048576
#define GG 32
#define SS 2048
#define HH 128
#define CC 40

// ---------------- scratch (device globals; no runtime allocation) ----------
__device__ __align__(16) __nv_bfloat16 g_xhi[(size_t)NN * HH];
__device__ __align__(16) __nv_bfloat16 g_xlo[(size_t)NN * HH];
__device__ __align__(16) __nv_bfloat16 g_pAhi[(size_t)NN * HH];
__device__ __align__(16) __nv_bfloat16 g_pAlo[(size_t)NN * HH];
__device__ __align__(16) __nv_bfloat16 g_pBhi[(size_t)NN * HH];
__device__ __align__(16) __nv_bfloat16 g_pBlo[(size_t)NN * HH];
__device__ __align__(16) __nv_bfloat16 g_wdynhi[GG * HH * HH];
__device__ __align__(16) __nv_bfloat16 g_wdynlo[GG * HH * HH];
__device__ __align__(16) __nv_bfloat16 g_cwhi[3 * HH * HH];
__device__ __align__(16) __nv_bfloat16 g_cwlo[3 * HH * HH];
__device__ __align__(16) __half g_hw[(size_t)NN * HH];   // 16 MB, pre-scaled by dis
__device__ float  g_dis[NN];
__device__ int    g_counts[NN];
__device__ int    g_off[NN + 1];
__device__ int    g_cursor[NN];
__device__ int    g_col[EE];               // 4 MB
__device__ int    g_blocksum[256];
__device__ int    g_is64;

// ---------------- helpers ----------------------------------------------------
__device__ __forceinline__ uint32_t smem_to_u32(const void* p) {
    uint32_t a;
    asm("{ .reg .u64 t; cvta.to.shared.u64 t, %1; cvt.u32.u64 %0, t; }"
        : "=r"(a) : "l"(p));
    return a;
}
__device__ __forceinline__ uint64_t gptr(const void* p) {
    uint64_t r;
    asm("cvta.to.global.u64 %0, %1;" : "=l"(r) : "l"(p));
    return r;
}
#define CP_ASYNC16(dst, src) \
    asm volatile("cp.async.cg.shared.global [%0], [%1], 16;" \
        :: "r"(dst), "l"(src))
#define CP_COMMIT()  asm volatile("cp.async.commit_group;")
#define CP_WAIT0()   asm volatile("cp.async.wait_group 0;" ::: "memory")

#define LDSM_X4(r0, r1, r2, r3, addr) \
    asm volatile("ldmatrix.sync.aligned.m8n8.x4.shared.b16 {%0,%1,%2,%3}, [%4];" \
        : "=r"(r0), "=r"(r1), "=r"(r2), "=r"(r3) : "r"(addr))
#define LDSM_X4_T(r0, r1, r2, r3, addr) \
    asm volatile("ldmatrix.sync.aligned.m8n8.x4.trans.shared.b16 {%0,%1,%2,%3}, [%4];" \
        : "=r"(r0), "=r"(r1), "=r"(r2), "=r"(r3) : "r"(addr))
#define MMA_BF16(d, a, b0v, b1v) \
    asm volatile("mma.sync.aligned.m16n8k16.row.col.f32.bf16.bf16.f32 " \
        "{%0,%1,%2,%3}, {%4,%5,%6,%7}, {%8,%9}, {%0,%1,%2,%3};" \
        : "+f"((d)[0]), "+f"((d)[1]), "+f"((d)[2]), "+f"((d)[3]) \
        : "r"((a)[0]), "r"((a)[1]), "r"((a)[2]), "r"((a)[3]), \
          "r"(b0v), "r"(b1v))

__device__ __forceinline__ uint32_t pack_bf16x2(float e0, float e1) {
    uint32_t r;
    asm("cvt.rn.bf16x2.f32 %0, %1, %2;" : "=r"(r) : "f"(e1), "f"(e0));
    return r;
}
__device__ __forceinline__ void split2(float e0, float e1,
                                       uint32_t& hi, uint32_t& lo) {
    float h0 = __bfloat162float(__float2bfloat16_rn(e0));
    float h1 = __bfloat162float(__float2bfloat16_rn(e1));
    hi = pack_bf16x2(h0, h1);
    lo = pack_bf16x2(e0 - h0, e1 - h1);
}

// ---------------- preprocessing kernels -------------------------------------
__global__ void wdyn_kernel(const float* __restrict__ w0,
                            const float* __restrict__ b0,
                            const float* __restrict__ emeta,
                            const int* __restrict__ ei) {
    int idx = blockIdx.x * blockDim.x + threadIdx.x;
    if (idx < NN) g_counts[idx] = 0;
    if (blockIdx.x == 0 && threadIdx.x < 32) {
        int nz = 0;
#pragma unroll
        for (int q = 0; q < 4; q++) nz |= ei[1 + 2 * (threadIdx.x + q * 32)];
        unsigned any = __ballot_sync(0xFFFFFFFFu, nz != 0);
        if (threadIdx.x == 0) g_is64 = (any == 0);
    }
    if (idx >= GG * HH * HH / 2) return;
    int base = idx * 2;
    int g   = base >> 14;
    int rem = base & 16383;
    int f   = rem >> 7;
    int h   = rem & 127;
    float ga = emeta[g * HH + h];
    float gb = emeta[g * HH + h + 1];
    float v0 = fmaxf(fmaf(w0[f], ga, b0[rem]), 0.0f);
    float v1 = fmaxf(fmaf(w0[f], gb, b0[rem + 1]), 0.0f);
    uint32_t hi, lo;
    split2(v0, v1, hi, lo);
    ((uint32_t*)g_wdynhi)[idx] = hi;
    ((uint32_t*)g_wdynlo)[idx] = lo;
}

__device__ __forceinline__ int load_idx(const void* ei, long long pos) {
    if (g_is64) return (int)((const long long*)ei)[pos];
    return ((const int*)ei)[pos];
}

// split x + conv_w into hi/lo bf16 AND count edge in-degrees (fused)
#define XQ (NN * HH / 4)
#define WQ (3 * HH * HH / 4)
#define SPLIT_THREADS (XQ + WQ)
#define SPLIT_BLOCKS ((SPLIT_THREADS + 255) / 256)
__global__ void split_xw_count_kernel(const float* __restrict__ x,
                                      const float* __restrict__ cw,
                                      const void* __restrict__ ei) {
    int i = blockIdx.x * blockDim.x + threadIdx.x;
    if (i < XQ) {
        float4 v = ((const float4*)x)[i];
        uint32_t h01, l01, h23, l23;
        split2(v.x, v.y, h01, l01);
        split2(v.z, v.w, h23, l23);
        ((uint2*)g_xhi)[i] = make_uint2(h01, h23);
        ((uint2*)g_xlo)[i] = make_uint2(l01, l23);
    } else if (i < XQ + WQ) {
        int j = i - XQ;
        float4 v = ((const float4*)cw)[j];
        uint32_t h01, l01, h23, l23;
        split2(v.x, v.y, h01, l01);
        split2(v.z, v.w, h23, l23);
        ((uint2*)g_cwhi)[j] = make_uint2(h01, h23);
        ((uint2*)g_cwlo)[j] = make_uint2(l01, l23);
    }
    // in-degree counting, strided over all launched threads
    int nthreads = SPLIT_BLOCKS * 256;
    for (long long e = i; e < EE; e += nthreads) {
        int d = load_idx(ei, (long long)EE + e);
        atomicAdd(&g_counts[d], 1);
    }
}

// ---- hierarchical scan (A: per-block sums, C: merged scan + expand) --------
__global__ void scanA_kernel() {
    __shared__ int sh[256];
    int t = threadIdx.x;
    int v = g_counts[blockIdx.x * 256 + t];
    sh[t] = v;
    __syncthreads();
    for (int d = 128; d > 0; d >>= 1) {
        if (t < d) sh[t] += sh[t + d];
        __syncthreads();
    }
    if (t == 0) g_blocksum[blockIdx.x] = sh[0];
}

__global__ void scanC_kernel() {
    __shared__ int sh[256];
    __shared__ int sPre;
    __shared__ int sTot;
    int t = threadIdx.x;

    int bs = g_blocksum[t];
    sh[t] = (t < blockIdx.x) ? bs : 0;
    __syncthreads();
    for (int d = 128; d > 0; d >>= 1) {
        if (t < d) sh[t] += sh[t + d];
        __syncthreads();
    }
    if (t == 0) sPre = sh[0];
    __syncthreads();
    sh[t] = bs;
    __syncthreads();
    for (int d = 128; d > 0; d >>= 1) {
        if (t < d) sh[t] += sh[t + d];
        __syncthreads();
    }
    if (t == 0) sTot = sh[0];
    __syncthreads();

    int i = blockIdx.x * 256 + t;
    int c = g_counts[i];
    sh[t] = c;
    __syncthreads();
    for (int d = 1; d < 256; d <<= 1) {
        int v = 0;
        if (t >= d) v = sh[t - d];
        __syncthreads();
        sh[t] += v;
        __syncthreads();
    }
    int run = sPre + sh[t] - c;
    g_off[i]    = run;
    g_cursor[i] = run;
    g_dis[i]    = rsqrtf((float)(c + 1));
    if (blockIdx.x == 255 && t == 255) g_off[NN] = sTot;
}

__global__ void fill_kernel(const void* __restrict__ ei) {
    int e = blockIdx.x * blockDim.x + threadIdx.x;
    if (e >= EE) return;
    int sidx = load_idx(ei, e);
    int d    = load_idx(ei, (long long)EE + e);
    int p = atomicAdd(&g_cursor[d], 1);
    g_col[p] = sidx;
}

// ---------------- shared GEMM compute (64Mx128N tile, split-bf16) -----------
__device__ __forceinline__ void gemm_tile_compute(
    uint32_t sb, uint32_t aHiOff, uint32_t aLoOff,
    uint32_t bHiOff, uint32_t bLoOff,
    int lane, int m0, int n0, float acc[2][4][4]) {
    int lr = lane & 15;
    int hc = lane >> 4;
    int sx = lane & 7;
#pragma unroll
    for (int ks = 0; ks < 8; ks++) {
        int k0 = ks * 16;
        int chA = ((k0 >> 3) + hc) ^ sx;

        uint32_t aH[2][4], aL[2][4];
#pragma unroll
        for (int mi = 0; mi < 2; mi++) {
            int r = m0 + mi * 16 + lr;
            uint32_t off = (uint32_t)(r * 256 + (chA << 4));
            LDSM_X4(aH[mi][0], aH[mi][1], aH[mi][2], aH[mi][3],
                    sb + aHiOff + off);
            LDSM_X4(aL[mi][0], aL[mi][1], aL[mi][2], aL[mi][3],
                    sb + aLoOff + off);
        }
        uint32_t bH[2][4], bL[2][4];
#pragma unroll
        for (int bi = 0; bi < 2; bi++) {
            int r = k0 + lr;
            int ch = ((n0 >> 3) + bi * 2 + hc) ^ sx;
            uint32_t off = (uint32_t)(r * 256 + (ch << 4));
            LDSM_X4_T(bH[bi][0], bH[bi][1], bH[bi][2], bH[bi][3],
                      sb + bHiOff + off);
            LDSM_X4_T(bL[bi][0], bL[bi][1], bL[bi][2], bL[bi][3],
                      sb + bLoOff + off);
        }
#pragma unroll
        for (int mi = 0; mi < 2; mi++)
#pragma unroll
            for (int ni = 0; ni < 4; ni++) {
                uint32_t bh0 = bH[ni >> 1][(ni & 1) * 2 + 0];
                uint32_t bh1 = bH[ni >> 1][(ni & 1) * 2 + 1];
                uint32_t bl0 = bL[ni >> 1][(ni & 1) * 2 + 0];
                uint32_t bl1 = bL[ni >> 1][(ni & 1) * 2 + 1];
                MMA_BF16(acc[mi][ni], aH[mi], bh0, bh1);
                MMA_BF16(acc[mi][ni], aL[mi], bh0, bh1);
                MMA_BF16(acc[mi][ni], aH[mi], bl0, bl1);
            }
    }
}

// ---------------- gemm0: per-group B, pair output (round-12 form) -----------
#define AHI_OFF 0
#define ALO_OFF 16384
#define BHI_OFF 32768
#define BLO_OFF 65536
#define GEMM_SMEM 98304

__global__ void __launch_bounds__(256, 2)
gemm_mma_kernel(const __nv_bfloat16* __restrict__ Ahi,
                const __nv_bfloat16* __restrict__ Alo,
                const __nv_bfloat16* __restrict__ Bhi,
                const __nv_bfloat16* __restrict__ Blo,
                __nv_bfloat16* __restrict__ Chi,
                __nv_bfloat16* __restrict__ Clo,
                int rowsPerGy, int bStride) {
    extern __shared__ char smchar[];
    uint32_t sb = smem_to_u32(smchar);
    int t = threadIdx.x;
    int wid = t >> 5;
    int lane = t & 31;

    size_t bOff = (size_t)blockIdx.y * bStride;
    size_t row0 = (size_t)blockIdx.y * rowsPerGy + (size_t)blockIdx.x * 64;

#pragma unroll
    for (int q = 0; q < 4; q++) {
        int idx = t + q * 256;
        int row = idx >> 4;
        int ch  = idx & 15;
        uint32_t off = (uint32_t)(row * 256 + ((ch ^ (row & 7)) << 4));
        size_t gsrc = (row0 + row) * HH + ch * 8;
        CP_ASYNC16(sb + AHI_OFF + off, gptr(Ahi + gsrc));
        CP_ASYNC16(sb + ALO_OFF + off, gptr(Alo + gsrc));
    }
#pragma unroll
    for (int q = 0; q < 8; q++) {
        int idx = t + q * 256;
        int row = idx >> 4;
        int ch  = idx & 15;
        uint32_t off = (uint32_t)(row * 256 + ((ch ^ (row & 7)) << 4));
        size_t gsrc = bOff + (size_t)row * HH + ch * 8;
        CP_ASYNC16(sb + BHI_OFF + off, gptr(Bhi + gsrc));
        CP_ASYNC16(sb + BLO_OFF + off, gptr(Blo + gsrc));
    }
    CP_COMMIT();
    CP_WAIT0();
    __syncthreads();

    int m0 = (wid >> 2) * 32;
    int n0 = (wid & 3) * 32;

    float acc[2][4][4];
#pragma unroll
    for (int mi = 0; mi < 2; mi++)
#pragma unroll
        for (int ni = 0; ni < 4; ni++)
#pragma unroll
            for (int j = 0; j < 4; j++) acc[mi][ni][j] = 0.0f;

    gemm_tile_compute(sb, AHI_OFF, ALO_OFF, BHI_OFF, BLO_OFF,
                      lane, m0, n0, acc);

    int erow = lane >> 2;
    int ecol = (lane & 3) * 2;
#pragma unroll
    for (int mi = 0; mi < 2; mi++)
#pragma unroll
        for (int ni = 0; ni < 4; ni++) {
            size_t r = row0 + m0 + mi * 16 + erow;
            int c = n0 + ni * 8 + ecol;
            uint32_t hi, lo;
            split2(acc[mi][ni][0], acc[mi][ni][1], hi, lo);
            *(uint32_t*)(Chi + r * HH + c) = hi;
            *(uint32_t*)(Clo + r * HH + c) = lo;
            split2(acc[mi][ni][2], acc[mi][ni][3], hi, lo);
            *(uint32_t*)(Chi + (r + 8) * HH + c) = hi;
            *(uint32_t*)(Clo + (r + 8) * HH + c) = lo;
        }
}

// ---------------- conv GEMM: persistent, B resident, fp16*dis output --------
#define CB_HI 0
#define CB_LO 32768
#define CA_HI 65536
#define CA_LO 81920
#define NTILES (NN / 64)
#define CONV_GRID 296

__device__ __forceinline__ void conv_load_A(
    uint32_t sb, const __nv_bfloat16* Ahi, const __nv_bfloat16* Alo,
    int t, size_t row0) {
#pragma unroll
    for (int q = 0; q < 4; q++) {
        int idx = t + q * 256;
        int row = idx >> 4;
        int ch  = idx & 15;
        uint32_t off = (uint32_t)(row * 256 + ((ch ^ (row & 7)) << 4));
        size_t gsrc = (row0 + row) * HH + ch * 8;
        CP_ASYNC16(sb + CA_HI + off, gptr(Ahi + gsrc));
        CP_ASYNC16(sb + CA_LO + off, gptr(Alo + gsrc));
    }
    CP_COMMIT();
}

__global__ void __launch_bounds__(256, 2)
gemm_conv_kernel(const __nv_bfloat16* __restrict__ Ahi,
                 const __nv_bfloat16* __restrict__ Alo,
                 const __nv_bfloat16* __restrict__ Bhi,
                 const __nv_bfloat16* __restrict__ Blo,
                 __half* __restrict__ C) {
    extern __shared__ char smchar[];
    uint32_t sb = smem_to_u32(smchar);
    int t = threadIdx.x;
    int wid = t >> 5;
    int lane = t & 31;
    int m0 = (wid >> 2) * 32;
    int n0 = (wid & 3) * 32;
    int erow = lane >> 2;
    int ecol = (lane & 3) * 2;

    // resident B load (once)
#pragma unroll
    for (int q = 0; q < 8; q++) {
        int idx = t + q * 256;
        int row = idx >> 4;
        int ch  = idx & 15;
        uint32_t off = (uint32_t)(row * 256 + ((ch ^ (row & 7)) << 4));
        size_t gsrc = (size_t)row * HH + ch * 8;
        CP_ASYNC16(sb + CB_HI + off, gptr(Bhi + gsrc));
        CP_ASYNC16(sb + CB_LO + off, gptr(Blo + gsrc));
    }
    CP_COMMIT();

    int tile = blockIdx.x;
    conv_load_A(sb, Ahi, Alo, t, (size_t)tile * 64);

    for (; tile < NTILES; tile += CONV_GRID) {
        size_t row0 = (size_t)tile * 64;
        CP_WAIT0();
        __syncthreads();

        float acc[2][4][4];
#pragma unroll
        for (int mi = 0; mi < 2; mi++)
#pragma unroll
            for (int ni = 0; ni < 4; ni++)
#pragma unroll
                for (int j = 0; j < 4; j++) acc[mi][ni][j] = 0.0f;

        gemm_tile_compute(sb, CA_HI, CA_LO, CB_HI, CB_LO,
                          lane, m0, n0, acc);
        __syncthreads();

        int next = tile + CONV_GRID;
        if (next < NTILES)
            conv_load_A(sb, Ahi, Alo, t, (size_t)next * 64);

#pragma unroll
        for (int mi = 0; mi < 2; mi++) {
            size_t rb = row0 + m0 + mi * 16 + erow;
            float dr  = g_dis[rb];
            float dr8 = g_dis[rb + 8];
#pragma unroll
            for (int ni = 0; ni < 4; ni++) {
                int c = n0 + ni * 8 + ecol;
                *(__half2*)(C + rb * HH + c) =
                    __floats2half2_rn(acc[mi][ni][0] * dr,
                                      acc[mi][ni][1] * dr);
                *(__half2*)(C + (rb + 8) * HH + c) =
                    __floats2half2_rn(acc[mi][ni][2] * dr8,
                                      acc[mi][ni][3] * dr8);
            }
        }
    }
}

// ---------------- aggregation: pure gather-sum, 8-deep ----------------------
__global__ void agg_kernel(const __half* __restrict__ hw,
                           const float* __restrict__ bias,
                           __nv_bfloat16* __restrict__ outhi,
                           __nv_bfloat16* __restrict__ outlo) {
    int warp = (blockIdx.x * blockDim.x + threadIdx.x) >> 5;
    int lane = threadIdx.x & 31;
    if (warp >= NN) return;
    int i = warp;
    float di = g_dis[i];

    uint2 ua = ((const uint2*)(hw + (size_t)i * HH))[lane];
    float2 a0 = __half22float2(*(__half2*)&ua.x);
    float2 a1 = __half22float2(*(__half2*)&ua.y);
    float4 acc = make_float4(a0.x, a0.y, a1.x, a1.y);

    int e0 = g_off[i], e1 = g_off[i + 1];
    int e = e0;
    for (; e + 8 <= e1; e += 8) {
        int s[8];
#pragma unroll
        for (int q = 0; q < 8; q++) s[q] = g_col[e + q];
        uint2 u[8];
#pragma unroll
        for (int q = 0; q < 8; q++)
            u[q] = ((const uint2*)(hw + (size_t)s[q] * HH))[lane];
#pragma unroll
        for (int q = 0; q < 8; q++) {
            float2 p = __half22float2(*(__half2*)&u[q].x);
            float2 r = __half22float2(*(__half2*)&u[q].y);
            acc.x += p.x; acc.y += p.y; acc.z += r.x; acc.w += r.y;
        }
    }
    if (e + 4 <= e1) {
        int s[4];
#pragma unroll
        for (int q = 0; q < 4; q++) s[q] = g_col[e + q];
        uint2 u[4];
#pragma unroll
        for (int q = 0; q < 4; q++)
            u[q] = ((const uint2*)(hw + (size_t)s[q] * HH))[lane];
#pragma unroll
        for (int q = 0; q < 4; q++) {
            float2 p = __half22float2(*(__half2*)&u[q].x);
            float2 r = __half22float2(*(__half2*)&u[q].y);
            acc.x += p.x; acc.y += p.y; acc.z += r.x; acc.w += r.y;
        }
        e += 4;
    }
    for (; e < e1; e++) {
        uint2 u = ((const uint2*)(hw + (size_t)g_col[e] * HH))[lane];
        float2 p = __half22float2(*(__half2*)&u.x);
        float2 r = __half22float2(*(__half2*)&u.y);
        acc.x += p.x; acc.y += p.y; acc.z += r.x; acc.w += r.y;
    }

    float4 b = ((const float4*)bias)[lane];
    acc.x = fmaxf(fmaf(acc.x, di, b.x), 0.0f);
    acc.y = fmaxf(fmaf(acc.y, di, b.y), 0.0f);
    acc.z = fmaxf(fmaf(acc.z, di, b.z), 0.0f);
    acc.w = fmaxf(fmaf(acc.w, di, b.w), 0.0f);

    uint32_t h01, l01, h23, l23;
    split2(acc.x, acc.y, h01, l01);
    split2(acc.z, acc.w, h23, l23);
    size_t o = (size_t)i * HH + lane * 4;
    *(uint2*)(outhi + o) = make_uint2(h01, h23);
    *(uint2*)(outlo + o) = make_uint2(l01, l23);
}

// ---------------- final: logits + log_softmax (reads hi/lo pair) ------------
__global__ void final_kernel(const __nv_bfloat16* __restrict__ hhi,
                             const __nv_bfloat16* __restrict__ hlo,
                             const float* __restrict__ w,
                             const float* __restrict__ b,
                             float* __restrict__ out) {
    __shared__ float sWt[HH * CC];
    __shared__ float sB[CC];
    __shared__ float sH[16 * HH];
    __shared__ float sL[16 * CC];
    __shared__ float sLse[16];
    int t = threadIdx.x;
    for (int idx = t; idx < CC * HH; idx += 256) {
        int j = idx / HH, k = idx % HH;
        sWt[k * CC + j] = w[idx];
    }
    if (t < CC) sB[t] = b[t];
    size_t node0 = (size_t)blockIdx.x * 16;
    const uint2* hv = (const uint2*)(hhi + node0 * HH);
    const uint2* lv = (const uint2*)(hlo + node0 * HH);
    for (int i = t; i < 16 * HH / 4; i += 256) {
        uint2 hh = hv[i];
        uint2 ll = lv[i];
        __nv_bfloat162 h0 = *(__nv_bfloat162*)&hh.x;
        __nv_bfloat162 h1 = *(__nv_bfloat162*)&hh.y;
        __nv_bfloat162 l0 = *(__nv_bfloat162*)&ll.x;
        __nv_bfloat162 l1 = *(__nv_bfloat162*)&ll.y;
        sH[i * 4 + 0] = __bfloat162float(h0.x) + __bfloat162float(l0.x);
        sH[i * 4 + 1] = __bfloat162float(h0.y) + __bfloat162float(l0.y);
        sH[i * 4 + 2] = __bfloat162float(h1.x) + __bfloat162float(l1.x);
        sH[i * 4 + 3] = __bfloat162float(h1.y) + __bfloat162float(l1.y);
    }
    __syncthreads();

    for (int idx = t; idx < 16 * CC; idx += 256) {
        int n = idx / CC, j = idx % CC;
        float s = sB[j];
        const float* hr = &sH[n * HH];
#pragma unroll 8
        for (int k = 0; k < HH; k++)
            s = fmaf(hr[k], sWt[k * CC + j], s);
        sL[idx] = s;
    }
    __syncthreads();

    int wp = t >> 5, ln = t & 31;
    for (int n = wp; n < 16; n += 8) {
        float m = -INFINITY;
        for (int j = ln; j < CC; j += 32) m = fmaxf(m, sL[n * CC + j]);
        for (int o = 16; o > 0; o >>= 1) m = fmaxf(m, __shfl_xor_sync(~0u, m, o));
        float s = 0.0f;
        for (int j = ln; j < CC; j += 32) s += expf(sL[n * CC + j] - m);
        for (int o = 16; o > 0; o >>= 1) s += __shfl_xor_sync(~0u, s, o);
        if (ln == 0) sLse[n] = m + logf(s);
    }
    __syncthreads();

    for (int idx = t; idx < 16 * CC; idx += 256) {
        int n = idx / CC;
        out[node0 * CC + idx] = sL[idx] - sLse[n];
    }
}

// ---------------- launch ----------------------------------------------------
extern "C" void kernel_launch(void* const* d_in, const int* in_sizes, int n_in,
                              void* d_out, int out_size) {
    const float* x     = (const float*)d_in[0];
    const void*  ei    = d_in[1];
    const float* emeta = (const float*)d_in[2];
    const float* w0    = (const float*)d_in[4];
    const float* b0    = (const float*)d_in[5];
    const float* convw = (const float*)d_in[6];
    const float* convb = (const float*)d_in[7];
    const float* ltw   = (const float*)d_in[8];
    const float* ltb   = (const float*)d_in[9];
    float* out = (float*)d_out;

    __nv_bfloat16 *xhi, *xlo, *pAhi, *pAlo, *pBhi, *pBlo;
    __nv_bfloat16 *wdhi, *wdlo, *cwhi, *cwlo;
    __half *hw;
    cudaGetSymbolAddress((void**)&xhi,  g_xhi);
    cudaGetSymbolAddress((void**)&xlo,  g_xlo);
    cudaGetSymbolAddress((void**)&pAhi, g_pAhi);
    cudaGetSymbolAddress((void**)&pAlo, g_pAlo);
    cudaGetSymbolAddress((void**)&pBhi, g_pBhi);
    cudaGetSymbolAddress((void**)&pBlo, g_pBlo);
    cudaGetSymbolAddress((void**)&wdhi, g_wdynhi);
    cudaGetSymbolAddress((void**)&wdlo, g_wdynlo);
    cudaGetSymbolAddress((void**)&cwhi, g_cwhi);
    cudaGetSymbolAddress((void**)&cwlo, g_cwlo);
    cudaGetSymbolAddress((void**)&hw,   g_hw);

    cudaFuncSetAttribute(gemm_mma_kernel,
                         cudaFuncAttributeMaxDynamicSharedMemorySize, GEMM_SMEM);
    cudaFuncSetAttribute(gemm_conv_kernel,
                         cudaFuncAttributeMaxDynamicSharedMemorySize, GEMM_SMEM);

    // slot 3 = gemm0 for ncu (control)
    wdyn_kernel<<<(GG * HH * HH / 2 + 255) / 256, 256>>>(w0, b0, emeta,
                                                         (const int*)ei);  // 0
    split_xw_count_kernel<<<SPLIT_BLOCKS, 256>>>(x, convw, ei);            // 1
    scanA_kernel<<<256, 256>>>();                                          // 2
    gemm_mma_kernel<<<dim3(SS / 64, GG), 256, GEMM_SMEM>>>(                // 3
        xhi, xlo, wdhi, wdlo, pAhi, pAlo, SS, HH * HH);
    scanC_kernel<<<256, 256>>>();                                          // 4
    fill_kernel<<<EE / 256, 256>>>(ei);                                    // 5

    // 3 GCN layers (persistent conv GEMM, B resident)
    __nv_bfloat16* curhi = pAhi; __nv_bfloat16* curlo = pAlo;
    __nv_bfloat16* nxthi = pBhi; __nv_bfloat16* nxtlo = pBlo;
    for (int l = 0; l < 3; l++) {
        gemm_conv_kernel<<<CONV_GRID, 256, GEMM_SMEM>>>(
            curhi, curlo, cwhi + (size_t)l * HH * HH, cwlo + (size_t)l * HH * HH,
            hw);
        agg_kernel<<<NN / 8, 256>>>(hw, convb + (size_t)l * HH, nxthi, nxtlo);
        __nv_bfloat16* th = curhi; curhi = nxthi; nxthi = th;
        __nv_bfloat16* tl = curlo; curlo = nxtlo; nxtlo = tl;
    }

    // logits + log_softmax
    final_kernel<<<NN / 16, 256>>>(curhi, curlo, ltw, ltb, out);
}